// round 14
// baseline (speedup 1.0000x reference)
#include <cuda_runtime.h>
#include <cuda_fp16.h>
#include <cstdint>
#include <math.h>

// Problem constants: B=128, S=512, I=128, Hd=512
#define IDIM    128
#define HDIM    512
#define G3      1536
#define MTOT    65536
#define SEQ     512
#define H_TAIL  33488896ull      // B*(S-1)*Hd

// Scratch (allocation-free rule: __device__ globals)
__device__ __half g_Wh[G3 * IDIM];     // fused fp16 weight W = w_ih @ w_emb
__device__ float  g_bias[G3];          // fused bias
__device__ __half g_X16[MTOT * IDIM];  // x pre-converted to fp16 (16.8 MB)

// ===========================================================================
// Single prologue launch, 704 blocks x 256 threads:
//   blocks [0,192)   : W = w_ih @ w_emb direct (8 g-rows, full K=512, smem-
//                      staged w_ih) + fused bias from the staged rows
//   blocks [192,704) : x -> fp16 (MLP-batched)
// No second launch, no partial round-trip, no barrier.
// ===========================================================================
__global__ void precomp_all(const float* __restrict__ x,
                            const float* __restrict__ w_ih,
                            const float* __restrict__ w_emb,
                            const float* __restrict__ b_emb,
                            const float* __restrict__ b_ih,
                            const float* __restrict__ b_hh) {
    __shared__ float wihs[8 * 512];           // 16 KB
    const int b = blockIdx.x, tid = threadIdx.x;

    if (b < 192) {
        // ---- W direct: rows g0..g0+7, K=512 ----
        const int g0 = b * 8;
        {
            const float4* src = (const float4*)(w_ih + (size_t)g0 * 512);
            float4* dstv = (float4*)wihs;     // 8*512 floats = 1024 float4
#pragma unroll
            for (int it = 0; it < 4; it++)
                dstv[tid + it * 256] = src[tid + it * 256];
        }
        __syncthreads();

        const int i = tid & 127, gh = (tid >> 7) * 4;   // half-block -> 4 rows
        float acc[4] = {0.f, 0.f, 0.f, 0.f};
#pragma unroll 8
        for (int h = 0; h < 512; h++) {
            const float we = w_emb[h * IDIM + i];
#pragma unroll
            for (int g = 0; g < 4; g++)
                acc[g] = fmaf(wihs[(gh + g) * 512 + h], we, acc[g]);
        }
#pragma unroll
        for (int g = 0; g < 4; g++)
            g_Wh[(size_t)(g0 + gh + g) * IDIM + i] = __float2half_rn(acc[g]);

        // ---- bias: warp w handles row g0+w (rows already staged) ----
        {
            const int w = tid >> 5, lane = tid & 31;
            float a = 0.f;
#pragma unroll
            for (int h = lane; h < 512; h += 32)
                a = fmaf(wihs[w * 512 + h], b_emb[h], a);
#pragma unroll
            for (int off = 16; off; off >>= 1)
                a += __shfl_xor_sync(0xffffffffu, a, off);
            if (lane == 0) {
                const int g = g0 + w;
                float v = a + b_ih[g];
                if (g < 1024) v += b_hh[g];   // fold b_hr / b_hz
                g_bias[g] = v;
            }
        }
    } else {
        // ---- x -> fp16: 512 blocks, 8 int4 outputs/thread, loads batched ----
        // total int4 = MTOT*IDIM/8 = 1,048,576 = 512 * 256 * 8
        const int base = (b - 192) * 2048 + tid;
        float4 f[16];
#pragma unroll
        for (int it = 0; it < 8; it++) {
            const int idx = base + it * 256;
            f[2 * it]     = ((const float4*)x)[2 * idx];
            f[2 * it + 1] = ((const float4*)x)[2 * idx + 1];
        }
#pragma unroll
        for (int it = 0; it < 8; it++) {
            const int idx = base + it * 256;
            __half2 p0 = __floats2half2_rn(f[2 * it].x,     f[2 * it].y);
            __half2 p1 = __floats2half2_rn(f[2 * it].z,     f[2 * it].w);
            __half2 p2 = __floats2half2_rn(f[2 * it + 1].x, f[2 * it + 1].y);
            __half2 p3 = __floats2half2_rn(f[2 * it + 1].z, f[2 * it + 1].w);
            int4 o;
            o.x = *(int*)&p0; o.y = *(int*)&p1; o.z = *(int*)&p2; o.w = *(int*)&p3;
            ((int4*)g_X16)[idx] = o;
        }
    }
}

// ===========================================================================
// asm helpers
// ===========================================================================
__device__ __forceinline__ uint32_t smem_u32(const void* p) {
    uint32_t a;
    asm("{ .reg .u64 t; cvta.to.shared.u64 t, %1; cvt.u32.u64 %0, t; }"
        : "=r"(a) : "l"(p));
    return a;
}
__device__ __forceinline__ void cp16(uint32_t dst, const void* src) {
    asm volatile("cp.async.cg.shared.global [%0], [%1], 16;"
                 :: "r"(dst), "l"(src) : "memory");
}
__device__ __forceinline__ void ldsm4(uint32_t* r, uint32_t addr) {
    asm volatile("ldmatrix.sync.aligned.m8n8.x4.shared.b16 {%0,%1,%2,%3}, [%4];\n"
                 : "=r"(r[0]), "=r"(r[1]), "=r"(r[2]), "=r"(r[3]) : "r"(addr));
}
__device__ __forceinline__ void mma16816(float* c, const uint32_t* a, const uint32_t* b) {
    asm volatile("mma.sync.aligned.m16n8k16.row.col.f32.f16.f16.f32 "
                 "{%0,%1,%2,%3}, {%4,%5,%6,%7}, {%8,%9}, {%0,%1,%2,%3};\n"
                 : "+f"(c[0]), "+f"(c[1]), "+f"(c[2]), "+f"(c[3])
                 : "r"(a[0]), "r"(a[1]), "r"(a[2]), "r"(a[3]), "r"(b[0]), "r"(b[1]));
}
__device__ __forceinline__ float tanh_ap(float x) {
    float y; asm("tanh.approx.f32 %0, %1;" : "=f"(y) : "f"(x)); return y;
}
__device__ __forceinline__ float fsigmoid(float x) {
    return fmaf(0.5f, tanh_ap(0.5f * x), 0.5f);
}

// ===========================================================================
// Persistent fused kernel (byte-identical logic to the proven 106.1us R12
// version): 3-stage rotation on 2 A-buffers:
//   wait fill(j) -> mainloop(j) -> issue fill(j+74) -> epilogue(j)
// grid = (8 hd, 37 slots) = 296 CTAs (2/SM). B pinned once (48KB).
// SMEM: [0,32768) A0, [32768,65536) A1, [65536,114688) B.
// Swizzle: 128B rows; 16B chunk index XOR (row&7).
// ===========================================================================
#define SMEM_BYTES 114688

__global__ __launch_bounds__(256, 2)
void fused_persist(const float* __restrict__ b_hh,
                   float* __restrict__ out) {
    extern __shared__ __align__(1024) char smem[];
    const uint32_t sb = smem_u32(smem);
    const uint32_t Bb = sb + 65536;

    const int tid  = threadIdx.x;
    const int hd0  = blockIdx.x * 64;
    const int slot = blockIdx.y;

    // ---- group 0: B tiles + first A tile ----
    {
        const char* ws = (const char*)g_Wh;
#pragma unroll
        for (int it = 0; it < 12; it++) {
            const int idx  = tid + it * 256;
            const int gate = idx >> 10;
            const int rem  = idx & 1023;
            const int r    = rem >> 4;
            const int ch   = rem & 15;
            const uint32_t dst = Bb + gate * 16384 + (ch >> 3) * 8192 + r * 128
                               + (((ch & 7) ^ (r & 7)) << 4);
            cp16(dst, ws + ((size_t)(gate * HDIM + hd0 + r) * IDIM + ch * 8) * 2);
        }
        const char* xs = (const char*)(g_X16 + (size_t)(slot * 128) * IDIM);
#pragma unroll
        for (int it = 0; it < 8; it++) {
            const int idx = tid + it * 256;
            const int row = idx >> 4, ch = idx & 15;
            const uint32_t dst = sb + (ch >> 3) * 16384 + row * 128
                               + (((ch & 7) ^ (row & 7)) << 4);
            cp16(dst, xs + idx * 16);
        }
        asm volatile("cp.async.commit_group;" ::: "memory");
    }
    // ---- group 1: second A tile (slot+37 < 512 always) ----
    {
        const char* xs = (const char*)(g_X16 + (size_t)((slot + 37) * 128) * IDIM);
#pragma unroll
        for (int it = 0; it < 8; it++) {
            const int idx = tid + it * 256;
            const int row = idx >> 4, ch = idx & 15;
            const uint32_t dst = sb + 32768 + (ch >> 3) * 16384 + row * 128
                               + (((ch & 7) ^ (row & 7)) << 4);
            cp16(dst, xs + idx * 16);
        }
        asm volatile("cp.async.commit_group;" ::: "memory");
    }

    // ---- per-lane constants ----
    const int lane = tid & 31, warp = tid >> 5;
    const int wm = warp & 3, wn = warp >> 2;
    const int ar = wm * 32 + (lane & 15);
    const uint32_t a_row = (uint32_t)ar * 128u;
    const uint32_t a7    = (uint32_t)(ar & 7) << 4;
    const uint32_t ahi   = (uint32_t)((lane >> 4) & 1) << 4;
    const int br = wn * 32 + (lane & 7) + (((lane >> 4) & 1) << 3);
    const uint32_t b_row = (uint32_t)br * 128u;
    const uint32_t b7    = (uint32_t)(br & 7) << 4;
    const uint32_t bhi   = (uint32_t)((lane >> 3) & 1) << 4;

    int cur = 0;
    for (int j = slot; j < 512; j += 37) {
        // wait for fill(j): keep <=1 newer group in flight, else drain fully
        if (j + 37 < 512) {
            asm volatile("cp.async.wait_group 1;" ::: "memory");
        } else {
            asm volatile("cp.async.wait_group 0;" ::: "memory");
        }
        __syncthreads();

        // ---- mainloop: three 128x64 gate GEMMs from buffer cur ----
        const uint32_t Ab = sb + cur * 32768;
        float acc[3][2][4][4];
#pragma unroll
        for (int g = 0; g < 3; g++)
#pragma unroll
            for (int mi = 0; mi < 2; mi++)
#pragma unroll
                for (int ni = 0; ni < 4; ni++)
#pragma unroll
                    for (int t = 0; t < 4; t++) acc[g][mi][ni][t] = 0.f;

#pragma unroll
        for (int kk = 0; kk < 8; kk++) {
            const uint32_t aoff = (uint32_t)(kk >> 2) * 16384u + a_row
                                + ((((uint32_t)(kk & 3) << 5) | ahi) ^ a7);
            uint32_t ah[2][4];
            ldsm4(ah[0], Ab + aoff);
            ldsm4(ah[1], Ab + aoff + 2048);          // mi=1: +16 rows
            const uint32_t boff = (uint32_t)(kk >> 2) * 8192u + b_row
                                + ((((uint32_t)(kk & 3) << 5) | bhi) ^ b7);
#pragma unroll
            for (int g = 0; g < 3; g++) {
#pragma unroll
                for (int p = 0; p < 2; p++) {
                    uint32_t bf[4];
                    ldsm4(bf, Bb + g * 16384 + boff + p * 2048);
#pragma unroll
                    for (int mi = 0; mi < 2; mi++) {
                        mma16816(acc[g][mi][2 * p],     ah[mi], bf);
                        mma16816(acc[g][mi][2 * p + 1], ah[mi], bf + 2);
                    }
                }
            }
        }
        __syncthreads();      // all warps done reading buffer `cur`

        // ---- issue fill(j+74) into buffer `cur` BEFORE epilogue ----
        if (j + 74 < 512) {
            const char* xs = (const char*)(g_X16 + (size_t)((j + 74) * 128) * IDIM);
#pragma unroll
            for (int it = 0; it < 8; it++) {
                const int idx = tid + it * 256;
                const int row = idx >> 4, ch = idx & 15;
                const uint32_t dst = Ab + (ch >> 3) * 16384 + row * 128
                                   + (((ch & 7) ^ (row & 7)) << 4);
                cp16(dst, xs + idx * 16);
            }
            asm volatile("cp.async.commit_group;" ::: "memory");
        }

        // ---- epilogue (overlaps the in-flight fill) ----
        const int m0 = j * 128;
#pragma unroll
        for (int ni = 0; ni < 4; ni++) {
            const int colL = wn * 32 + ni * 8 + (lane & 3) * 2;
            const int hd = hd0 + colL;
            const float br0 = __ldg(&g_bias[hd]);
            const float br1 = __ldg(&g_bias[hd + 1]);
            const float bz0 = __ldg(&g_bias[HDIM + hd]);
            const float bz1 = __ldg(&g_bias[HDIM + hd + 1]);
            const float bn0 = __ldg(&g_bias[2 * HDIM + hd]);
            const float bn1 = __ldg(&g_bias[2 * HDIM + hd + 1]);
            const float bh0 = __ldg(&b_hh[2 * HDIM + hd]);
            const float bh1 = __ldg(&b_hh[2 * HDIM + hd + 1]);
#pragma unroll
            for (int mi = 0; mi < 2; mi++) {
#pragma unroll
                for (int hseg = 0; hseg < 2; hseg++) {
                    const int m = m0 + wm * 32 + mi * 16 + (lane >> 2) + hseg * 8;
                    const float r0 = fsigmoid(acc[0][mi][ni][hseg * 2 + 0] + br0);
                    const float r1 = fsigmoid(acc[0][mi][ni][hseg * 2 + 1] + br1);
                    const float z0 = fsigmoid(acc[1][mi][ni][hseg * 2 + 0] + bz0);
                    const float z1 = fsigmoid(acc[1][mi][ni][hseg * 2 + 1] + bz1);
                    const float n0 = tanh_ap(acc[2][mi][ni][hseg * 2 + 0] + bn0 + r0 * bh0);
                    const float n1 = tanh_ap(acc[2][mi][ni][hseg * 2 + 1] + bn1 + r1 * bh1);
                    const float h0 = (1.f - z0) * n0;
                    const float h1 = (1.f - z1) * n1;

                    const int bb = m >> 9;
                    const int s  = m & 511;
                    size_t o;
                    if (s < SEQ - 1)
                        o = (size_t)(m - bb) * HDIM + hd;           // H[b,s,:]
                    else
                        o = H_TAIL + (size_t)bb * HDIM + hd;        // h_last
                    __stcs((float2*)(out + o), make_float2(h0, h1));
                }
            }
        }
        cur ^= 1;
    }
}

// ===========================================================================
extern "C" void kernel_launch(void* const* d_in, const int* in_sizes, int n_in,
                              void* d_out, int out_size) {
    const float* x     = (const float*)d_in[0];
    const float* w_emb = (const float*)d_in[1];
    const float* b_emb = (const float*)d_in[2];
    const float* w_ih  = (const float*)d_in[3];
    const float* b_ih  = (const float*)d_in[4];
    const float* b_hh  = (const float*)d_in[5];
    float* out = (float*)d_out;
    (void)in_sizes; (void)n_in; (void)out_size;

    cudaFuncSetAttribute(fused_persist, cudaFuncAttributeMaxDynamicSharedMemorySize,
                         SMEM_BYTES);

    precomp_all<<<704, 256>>>(x, w_ih, w_emb, b_emb, b_ih, b_hh);

    dim3 grid(HDIM / 64, 37);            // 296 persistent CTAs (2/SM)
    fused_persist<<<grid, 256, SMEM_BYTES>>>(b_hh, out);
}

// round 15
// speedup vs baseline: 1.1310x; 1.1310x over previous
#include <cuda_runtime.h>
#include <cuda_fp16.h>
#include <cstdint>
#include <math.h>

// Problem constants: B=128, S=512, I=128, Hd=512
#define IDIM    128
#define HDIM    512
#define G3      1536
#define MTOT    65536
#define SEQ     512
#define H_TAIL  33488896ull      // B*(S-1)*Hd

// Scratch (allocation-free rule: __device__ globals)
__device__ __half g_Wh[G3 * IDIM];          // fused fp16 weight W = w_ih @ w_emb
__device__ float  g_Wpart[4 * G3 * IDIM];   // K-split partials
__device__ float  g_bias[G3];               // fused bias
__device__ __half g_X16[MTOT * IDIM];       // x pre-converted to fp16 (16.8 MB)

// ===========================================================================
// Prologue (R12-proven): blocks [0,512) x->fp16, [512,1280) W partials,
// [1280,1472) fused bias. Concurrent in one launch.
// ===========================================================================
__global__ void precomp_all(const float* __restrict__ x,
                            const float* __restrict__ w_ih,
                            const float* __restrict__ w_emb,
                            const float* __restrict__ b_emb,
                            const float* __restrict__ b_ih,
                            const float* __restrict__ b_hh) {
    const int b = blockIdx.x, tid = threadIdx.x;
    if (b < 512) {
        // ---- x -> fp16: 8 int4 outputs/thread, 16 LDG.128 front-batched ----
        const int base = b * 2048 + tid;
        float4 f[16];
#pragma unroll
        for (int it = 0; it < 8; it++) {
            const int idx = base + it * 256;
            f[2 * it]     = ((const float4*)x)[2 * idx];
            f[2 * it + 1] = ((const float4*)x)[2 * idx + 1];
        }
#pragma unroll
        for (int it = 0; it < 8; it++) {
            const int idx = base + it * 256;
            __half2 p0 = __floats2half2_rn(f[2 * it].x,     f[2 * it].y);
            __half2 p1 = __floats2half2_rn(f[2 * it].z,     f[2 * it].w);
            __half2 p2 = __floats2half2_rn(f[2 * it + 1].x, f[2 * it + 1].y);
            __half2 p3 = __floats2half2_rn(f[2 * it + 1].z, f[2 * it + 1].w);
            int4 o;
            o.x = *(int*)&p0; o.y = *(int*)&p1; o.z = *(int*)&p2; o.w = *(int*)&p3;
            ((int4*)g_X16)[idx] = o;
        }
    } else if (b < 1280) {
        // ---- W partial: 8 g-rows x 128 i x 128 h-chunk ----
        __shared__ float wihs[8][128];
        const int q = b - 512;
        const int g0 = (q >> 2) * 8, h0 = (q & 3) * 128;
        {
            const float4* src = (const float4*)(w_ih + (size_t)g0 * 512 + h0);
            const int g = tid >> 5, c = tid & 31;
            ((float4*)&wihs[0][0])[g * 32 + c] = src[g * 128 + c];
        }
        __syncthreads();
        const int i = tid & 127, gh = (tid >> 7) * 4;
        float acc[4] = {0.f, 0.f, 0.f, 0.f};
#pragma unroll 8
        for (int h = 0; h < 128; h++) {
            const float we = w_emb[(h0 + h) * IDIM + i];
#pragma unroll
            for (int g = 0; g < 4; g++) acc[g] = fmaf(wihs[gh + g][h], we, acc[g]);
        }
        const int chunk = q & 3;
#pragma unroll
        for (int g = 0; g < 4; g++)
            g_Wpart[(size_t)chunk * (G3 * IDIM) + (size_t)(g0 + gh + g) * IDIM + i] = acc[g];
    } else {
        // ---- bias[g] = w_ih[g]·b_emb + b_ih[g] + (g<1024 ? b_hh[g] : 0) ----
        const int q = b - 1280;
        const int warp = tid >> 5, lane = tid & 31;
        const int g = q * 8 + warp;
        const float* wg = w_ih + (size_t)g * 512;
        float acc = 0.f;
#pragma unroll
        for (int h = lane; h < 512; h += 32) acc = fmaf(wg[h], b_emb[h], acc);
#pragma unroll
        for (int off = 16; off; off >>= 1) acc += __shfl_xor_sync(0xffffffffu, acc, off);
        if (lane == 0) {
            float v = acc + b_ih[g];
            if (g < 1024) v += b_hh[g];
            g_bias[g] = v;
        }
    }
}

__global__ void precomp_W_reduce() {
    const int v = blockIdx.x * 256 + threadIdx.x;
    const float4 a = ((const float4*)g_Wpart)[v];
    const float4 b = ((const float4*)g_Wpart)[v + 49152];
    const float4 c = ((const float4*)g_Wpart)[v + 2 * 49152];
    const float4 d = ((const float4*)g_Wpart)[v + 3 * 49152];
    __half2 h01 = __halves2half2(__float2half_rn(a.x + b.x + c.x + d.x),
                                 __float2half_rn(a.y + b.y + c.y + d.y));
    __half2 h23 = __halves2half2(__float2half_rn(a.z + b.z + c.z + d.z),
                                 __float2half_rn(a.w + b.w + c.w + d.w));
    ((__half2*)g_Wh)[v * 2]     = h01;
    ((__half2*)g_Wh)[v * 2 + 1] = h23;
}

// ===========================================================================
// asm helpers
// ===========================================================================
__device__ __forceinline__ uint32_t smem_u32(const void* p) {
    uint32_t a;
    asm("{ .reg .u64 t; cvta.to.shared.u64 t, %1; cvt.u32.u64 %0, t; }"
        : "=r"(a) : "l"(p));
    return a;
}
__device__ __forceinline__ void cp16(uint32_t dst, const void* src) {
    asm volatile("cp.async.cg.shared.global [%0], [%1], 16;"
                 :: "r"(dst), "l"(src) : "memory");
}
__device__ __forceinline__ void ldsm4(uint32_t* r, uint32_t addr) {
    asm volatile("ldmatrix.sync.aligned.m8n8.x4.shared.b16 {%0,%1,%2,%3}, [%4];\n"
                 : "=r"(r[0]), "=r"(r[1]), "=r"(r[2]), "=r"(r[3]) : "r"(addr));
}
__device__ __forceinline__ void mma16816(float* c, const uint32_t* a, const uint32_t* b) {
    asm volatile("mma.sync.aligned.m16n8k16.row.col.f32.f16.f16.f32 "
                 "{%0,%1,%2,%3}, {%4,%5,%6,%7}, {%8,%9}, {%0,%1,%2,%3};\n"
                 : "+f"(c[0]), "+f"(c[1]), "+f"(c[2]), "+f"(c[3])
                 : "r"(a[0]), "r"(a[1]), "r"(a[2]), "r"(a[3]), "r"(b[0]), "r"(b[1]));
}
__device__ __forceinline__ float tanh_ap(float x) {
    float y; asm("tanh.approx.f32 %0, %1;" : "=f"(y) : "f"(x)); return y;
}
__device__ __forceinline__ float fsigmoid(float x) {
    return fmaf(0.5f, tanh_ap(0.5f * x), 0.5f);
}

// ===========================================================================
// Persistent fused kernel (R12-proven pipeline) + anti-phase skew:
// second-wave CTAs (bid >= 148) delay ~4300 cycles so their epilogue (MUFU/
// store) overlaps the co-resident CTA's mainloop (HMMA) instead of colliding.
//   wait fill(j) -> mainloop(j) -> issue fill(j+74) -> epilogue(j)
// grid = (8 hd, 37 slots) = 296 CTAs (2/SM). B pinned once (48KB).
// SMEM: [0,32768) A0, [32768,65536) A1, [65536,114688) B.
// ===========================================================================
#define SMEM_BYTES 114688

__global__ __launch_bounds__(256, 2)
void fused_persist(const float* __restrict__ b_hh,
                   float* __restrict__ out) {
    extern __shared__ __align__(1024) char smem[];
    const uint32_t sb = smem_u32(smem);
    const uint32_t Bb = sb + 65536;

    const int tid  = threadIdx.x;
    const int hd0  = blockIdx.x * 64;
    const int slot = blockIdx.y;

    // ---- anti-phase skew for the second wave (co-resident CTA pair) ----
    {
        const int bid = blockIdx.x + 8 * blockIdx.y;
        if (bid >= 148) {
            const long long t0 = clock64();
            while (clock64() - t0 < 4300) { }
        }
    }

    // ---- group 0: B tiles + first A tile ----
    {
        const char* ws = (const char*)g_Wh;
#pragma unroll
        for (int it = 0; it < 12; it++) {
            const int idx  = tid + it * 256;
            const int gate = idx >> 10;
            const int rem  = idx & 1023;
            const int r    = rem >> 4;
            const int ch   = rem & 15;
            const uint32_t dst = Bb + gate * 16384 + (ch >> 3) * 8192 + r * 128
                               + (((ch & 7) ^ (r & 7)) << 4);
            cp16(dst, ws + ((size_t)(gate * HDIM + hd0 + r) * IDIM + ch * 8) * 2);
        }
        const char* xs = (const char*)(g_X16 + (size_t)(slot * 128) * IDIM);
#pragma unroll
        for (int it = 0; it < 8; it++) {
            const int idx = tid + it * 256;
            const int row = idx >> 4, ch = idx & 15;
            const uint32_t dst = sb + (ch >> 3) * 16384 + row * 128
                               + (((ch & 7) ^ (row & 7)) << 4);
            cp16(dst, xs + idx * 16);
        }
        asm volatile("cp.async.commit_group;" ::: "memory");
    }
    // ---- group 1: second A tile (slot+37 < 512 always) ----
    {
        const char* xs = (const char*)(g_X16 + (size_t)((slot + 37) * 128) * IDIM);
#pragma unroll
        for (int it = 0; it < 8; it++) {
            const int idx = tid + it * 256;
            const int row = idx >> 4, ch = idx & 15;
            const uint32_t dst = sb + 32768 + (ch >> 3) * 16384 + row * 128
                               + (((ch & 7) ^ (row & 7)) << 4);
            cp16(dst, xs + idx * 16);
        }
        asm volatile("cp.async.commit_group;" ::: "memory");
    }

    // ---- per-lane constants ----
    const int lane = tid & 31, warp = tid >> 5;
    const int wm = warp & 3, wn = warp >> 2;
    const int ar = wm * 32 + (lane & 15);
    const uint32_t a_row = (uint32_t)ar * 128u;
    const uint32_t a7    = (uint32_t)(ar & 7) << 4;
    const uint32_t ahi   = (uint32_t)((lane >> 4) & 1) << 4;
    const int br = wn * 32 + (lane & 7) + (((lane >> 4) & 1) << 3);
    const uint32_t b_row = (uint32_t)br * 128u;
    const uint32_t b7    = (uint32_t)(br & 7) << 4;
    const uint32_t bhi   = (uint32_t)((lane >> 3) & 1) << 4;

    int cur = 0;
    for (int j = slot; j < 512; j += 37) {
        // wait for fill(j): keep <=1 newer group in flight, else drain fully
        if (j + 37 < 512) {
            asm volatile("cp.async.wait_group 1;" ::: "memory");
        } else {
            asm volatile("cp.async.wait_group 0;" ::: "memory");
        }
        __syncthreads();

        // ---- mainloop: three 128x64 gate GEMMs from buffer cur ----
        const uint32_t Ab = sb + cur * 32768;
        float acc[3][2][4][4];
#pragma unroll
        for (int g = 0; g < 3; g++)
#pragma unroll
            for (int mi = 0; mi < 2; mi++)
#pragma unroll
                for (int ni = 0; ni < 4; ni++)
#pragma unroll
                    for (int t = 0; t < 4; t++) acc[g][mi][ni][t] = 0.f;

#pragma unroll
        for (int kk = 0; kk < 8; kk++) {
            const uint32_t aoff = (uint32_t)(kk >> 2) * 16384u + a_row
                                + ((((uint32_t)(kk & 3) << 5) | ahi) ^ a7);
            uint32_t ah[2][4];
            ldsm4(ah[0], Ab + aoff);
            ldsm4(ah[1], Ab + aoff + 2048);          // mi=1: +16 rows
            const uint32_t boff = (uint32_t)(kk >> 2) * 8192u + b_row
                                + ((((uint32_t)(kk & 3) << 5) | bhi) ^ b7);
#pragma unroll
            for (int g = 0; g < 3; g++) {
#pragma unroll
                for (int p = 0; p < 2; p++) {
                    uint32_t bf[4];
                    ldsm4(bf, Bb + g * 16384 + boff + p * 2048);
#pragma unroll
                    for (int mi = 0; mi < 2; mi++) {
                        mma16816(acc[g][mi][2 * p],     ah[mi], bf);
                        mma16816(acc[g][mi][2 * p + 1], ah[mi], bf + 2);
                    }
                }
            }
        }
        __syncthreads();      // all warps done reading buffer `cur`

        // ---- issue fill(j+74) into buffer `cur` BEFORE epilogue ----
        if (j + 74 < 512) {
            const char* xs = (const char*)(g_X16 + (size_t)((j + 74) * 128) * IDIM);
#pragma unroll
            for (int it = 0; it < 8; it++) {
                const int idx = tid + it * 256;
                const int row = idx >> 4, ch = idx & 15;
                const uint32_t dst = Ab + (ch >> 3) * 16384 + row * 128
                                   + (((ch & 7) ^ (row & 7)) << 4);
                cp16(dst, xs + idx * 16);
            }
            asm volatile("cp.async.commit_group;" ::: "memory");
        }

        // ---- epilogue (overlaps in-flight fill + peer CTA's mainloop) ----
        const int m0 = j * 128;
#pragma unroll
        for (int ni = 0; ni < 4; ni++) {
            const int colL = wn * 32 + ni * 8 + (lane & 3) * 2;
            const int hd = hd0 + colL;
            const float br0 = __ldg(&g_bias[hd]);
            const float br1 = __ldg(&g_bias[hd + 1]);
            const float bz0 = __ldg(&g_bias[HDIM + hd]);
            const float bz1 = __ldg(&g_bias[HDIM + hd + 1]);
            const float bn0 = __ldg(&g_bias[2 * HDIM + hd]);
            const float bn1 = __ldg(&g_bias[2 * HDIM + hd + 1]);
            const float bh0 = __ldg(&b_hh[2 * HDIM + hd]);
            const float bh1 = __ldg(&b_hh[2 * HDIM + hd + 1]);
#pragma unroll
            for (int mi = 0; mi < 2; mi++) {
#pragma unroll
                for (int hseg = 0; hseg < 2; hseg++) {
                    const int m = m0 + wm * 32 + mi * 16 + (lane >> 2) + hseg * 8;
                    const float r0 = fsigmoid(acc[0][mi][ni][hseg * 2 + 0] + br0);
                    const float r1 = fsigmoid(acc[0][mi][ni][hseg * 2 + 1] + br1);
                    const float z0 = fsigmoid(acc[1][mi][ni][hseg * 2 + 0] + bz0);
                    const float z1 = fsigmoid(acc[1][mi][ni][hseg * 2 + 1] + bz1);
                    const float n0 = tanh_ap(acc[2][mi][ni][hseg * 2 + 0] + bn0 + r0 * bh0);
                    const float n1 = tanh_ap(acc[2][mi][ni][hseg * 2 + 1] + bn1 + r1 * bh1);
                    const float h0 = (1.f - z0) * n0;
                    const float h1 = (1.f - z1) * n1;

                    const int bb = m >> 9;
                    const int s  = m & 511;
                    size_t o;
                    if (s < SEQ - 1)
                        o = (size_t)(m - bb) * HDIM + hd;           // H[b,s,:]
                    else
                        o = H_TAIL + (size_t)bb * HDIM + hd;        // h_last
                    __stcs((float2*)(out + o), make_float2(h0, h1));
                }
            }
        }
        cur ^= 1;
    }
}

// ===========================================================================
extern "C" void kernel_launch(void* const* d_in, const int* in_sizes, int n_in,
                              void* d_out, int out_size) {
    const float* x     = (const float*)d_in[0];
    const float* w_emb = (const float*)d_in[1];
    const float* b_emb = (const float*)d_in[2];
    const float* w_ih  = (const float*)d_in[3];
    const float* b_ih  = (const float*)d_in[4];
    const float* b_hh  = (const float*)d_in[5];
    float* out = (float*)d_out;
    (void)in_sizes; (void)n_in; (void)out_size;

    cudaFuncSetAttribute(fused_persist, cudaFuncAttributeMaxDynamicSharedMemorySize,
                         SMEM_BYTES);

    precomp_all<<<1472, 256>>>(x, w_ih, w_emb, b_emb, b_ih, b_hh);
    precomp_W_reduce<<<192, 256>>>();

    dim3 grid(HDIM / 64, 37);            // 296 persistent CTAs (2/SM)
    fused_persist<<<grid, 256, SMEM_BYTES>>>(b_hh, out);
}